// round 16
// baseline (speedup 1.0000x reference)
#include <cuda_runtime.h>
#include <math.h>
#include <stdint.h>

#define NTOK 1024          // B*S
#define HDIM 2048
#define NEXP 16
#define IDIM 1408

#define AP  20    // A smem pitch (BK=16 + 4)
#define BP1 72    // gemm1 B pitch (BN=64 + 8)
#define BP2 136   // gemm2 B pitch (BN=128 + 8)

// ---------------- scratch (static device globals; no allocations) ----------
__device__ int   g_cnt[NEXP];
__device__ int   g_tok[NEXP * NTOK];     // packed: token*2 + slot
__device__ float g_wt [NEXP * NTOK];     // renormalized routing weight
__device__ float g_act[2 * NTOK * IDIM]; // silu(g)*u per (token,slot)

// ---------------- helpers ---------------------------------------------------
__device__ __forceinline__ float tf32r(float x) {
    uint32_t u;
    asm("cvt.rna.tf32.f32 %0, %1;" : "=r"(u) : "f"(x));
    return __uint_as_float(u);
}
__device__ __forceinline__ float4 tf4(float4 v) {
    return make_float4(tf32r(v.x), tf32r(v.y), tf32r(v.z), tf32r(v.w));
}
__device__ __forceinline__ void mma8(float* d, const uint32_t* a, const uint32_t* b) {
    asm volatile("mma.sync.aligned.m16n8k8.row.col.f32.tf32.tf32.f32 "
                 "{%0,%1,%2,%3}, {%4,%5,%6,%7}, {%8,%9}, {%0,%1,%2,%3};"
                 : "+f"(d[0]), "+f"(d[1]), "+f"(d[2]), "+f"(d[3])
                 : "r"(a[0]), "r"(a[1]), "r"(a[2]), "r"(a[3]),
                   "r"(b[0]), "r"(b[1]));
}
__device__ __forceinline__ float silu_mul(float g, float u) {
    return (g / (1.f + expf(-g))) * u;
}

// ---------------- kernel 0: zero counters ----------------------------------
__global__ void zero_counts_kernel() {
    if (threadIdx.x < NEXP) g_cnt[threadIdx.x] = 0;
}

// ---------------- kernel 1: router (fp32) ----------------------------------
__global__ void router_kernel(const float* __restrict__ x,
                              const float* __restrict__ gw) {
    const int t = blockIdx.x;
    const float* xr = x + (size_t)t * HDIM;
    __shared__ float logits[NEXP];

    const int warp = threadIdx.x >> 5;
    const int lane = threadIdx.x & 31;

    for (int e = warp; e < NEXP; e += 8) {
        const float* w = gw + (size_t)e * HDIM;
        float s = 0.f;
        for (int k = lane; k < HDIM; k += 32)
            s = fmaf(xr[k], w[k], s);
        #pragma unroll
        for (int o = 16; o; o >>= 1) s += __shfl_xor_sync(0xffffffffu, s, o);
        if (lane == 0) logits[e] = s;
    }
    __syncthreads();

    if (threadIdx.x == 0) {
        int e1 = 0; float l1 = logits[0];
        #pragma unroll
        for (int e = 1; e < NEXP; e++)
            if (logits[e] > l1) { l1 = logits[e]; e1 = e; }
        int e2 = -1; float l2 = -INFINITY;
        #pragma unroll
        for (int e = 0; e < NEXP; e++)
            if (e != e1 && logits[e] > l2) { l2 = logits[e]; e2 = e; }
        float w1 = 1.f / (1.f + expf(l2 - l1));   // p1/(p1+p2)
        float w2 = 1.f - w1;
        int p1 = atomicAdd(&g_cnt[e1], 1);
        g_tok[e1 * NTOK + p1] = t * 2 + 0;
        g_wt [e1 * NTOK + p1] = w1;
        int p2 = atomicAdd(&g_cnt[e2], 1);
        g_tok[e2 * NTOK + p2] = t * 2 + 1;
        g_wt [e2 * NTOK + p2] = w2;
    }
}

// ============================================================================
// GEMM1: act[slot][i] = silu(x@Wg) * (x@Wu)
// BM=32, BN=64 (per matrix), BK=16, double-buffered, 1 sync per iter.
// 8 warps in 2(M)x4(N); warp tile 16x16 per matrix (mi=1, ni=2).
// ============================================================================
__global__ __launch_bounds__(256, 4)
void gemm1_tc(const float* __restrict__ x,
              const float* __restrict__ wg,
              const float* __restrict__ wu) {
    const int e   = blockIdx.z;
    const int cnt = g_cnt[e];
    const int m0  = blockIdx.y * 32;
    if (m0 >= cnt) return;
    const int n0  = blockIdx.x * 64;

    __shared__ __align__(16) float As[2][32 * AP];
    __shared__ __align__(16) float Bg[2][16 * BP1];
    __shared__ __align__(16) float Bu[2][16 * BP1];
    __shared__ int toks[32];

    const int tid = threadIdx.x;
    if (tid < 32) {
        int r = m0 + tid;
        toks[tid] = (r < cnt) ? g_tok[e * NTOK + r] : -1;
    }
    __syncthreads();

    // ---- loader setup
    const bool aload = (tid < 128);
    const int  am = tid >> 2;            // 0..31 (A rows)
    const int  ac = (tid & 3) * 4;       // 0,4,8,12
    const float* aptr = x;
    if (aload) {
        int pk = toks[am];
        aptr = x + (size_t)((pk >= 0 ? pk : 0) >> 1) * HDIM + ac;
    }
    const int bk = tid >> 4;             // 0..15
    const int bn = (tid & 15) * 4;       // 0..60
    const size_t bstep = (size_t)16 * IDIM;
    const float* gp = wg + (size_t)e * HDIM * IDIM + (size_t)bk * IDIM + n0 + bn;
    const float* up = wu + (size_t)e * HDIM * IDIM + (size_t)bk * IDIM + n0 + bn;

    // ---- mma mapping
    const int lane = tid & 31, wid = tid >> 5;
    const int mw = (wid & 1) * 16;
    const int nw = (wid >> 1) * 16;
    const int g  = lane >> 2, q = lane & 3;

    float accG[2][4] = {};
    float accU[2][4] = {};

    float4 rA = make_float4(0, 0, 0, 0), rG, rU;

    // prologue: tile 0 -> buf 0
    if (aload) rA = *(const float4*)aptr;
    rG = *(const float4*)gp;
    rU = *(const float4*)up;
    if (aload) *(float4*)&As[0][am * AP + ac] = tf4(rA);
    *(float4*)&Bg[0][bk * BP1 + bn] = tf4(rG);
    *(float4*)&Bu[0][bk * BP1 + bn] = tf4(rU);
    __syncthreads();

    int p = 0;
    for (int k0 = 0; k0 < HDIM; k0 += 16) {
        const bool more = (k0 + 16 < HDIM);
        if (more) {
            aptr += 16; gp += bstep; up += bstep;
            if (aload) rA = *(const float4*)aptr;
            rG = *(const float4*)gp;
            rU = *(const float4*)up;
        }

        #pragma unroll
        for (int kk = 0; kk < 16; kk += 8) {
            uint32_t a[4];
            const float* ab = &As[p][(mw + g) * AP + kk + q];
            a[0] = __float_as_uint(ab[0]);
            a[1] = __float_as_uint(ab[8 * AP]);
            a[2] = __float_as_uint(ab[4]);
            a[3] = __float_as_uint(ab[8 * AP + 4]);
            #pragma unroll
            for (int ni = 0; ni < 2; ni++) {
                const float* gb = &Bg[p][(kk + q) * BP1 + nw + ni * 8 + g];
                const float* ub = &Bu[p][(kk + q) * BP1 + nw + ni * 8 + g];
                uint32_t bg_[2] = { __float_as_uint(gb[0]), __float_as_uint(gb[4 * BP1]) };
                uint32_t bu_[2] = { __float_as_uint(ub[0]), __float_as_uint(ub[4 * BP1]) };
                mma8(accG[ni], a, bg_);
                mma8(accU[ni], a, bu_);
            }
        }

        if (more) {
            if (aload) *(float4*)&As[p ^ 1][am * AP + ac] = tf4(rA);
            *(float4*)&Bg[p ^ 1][bk * BP1 + bn] = tf4(rG);
            *(float4*)&Bu[p ^ 1][bk * BP1 + bn] = tf4(rU);
        }
        __syncthreads();
        p ^= 1;
    }

    // ---- epilogue: silu(g)*u -> g_act
    #pragma unroll
    for (int half = 0; half < 2; half++) {
        int row = mw + g + half * 8;
        int pk  = toks[row];
        if (pk < 0) continue;
        float* dst = g_act + (size_t)pk * IDIM + n0 + nw + 2 * q;
        #pragma unroll
        for (int ni = 0; ni < 2; ni++) {
            float o0 = silu_mul(accG[ni][half * 2 + 0], accU[ni][half * 2 + 0]);
            float o1 = silu_mul(accG[ni][half * 2 + 1], accU[ni][half * 2 + 1]);
            *(float2*)(dst + ni * 8) = make_float2(o0, o1);
        }
    }
}

// ============================================================================
// GEMM2: out[tok] += w * (act[slot] @ w_down[e])
// BM=32, BN=128, BK=16, double-buffered, 1 sync per iter.
// 8 warps in 2(M)x4(N); warp tile 16x32 (mi=1, ni=4).
// ============================================================================
__global__ __launch_bounds__(256, 4)
void gemm2_tc(const float* __restrict__ wd,
              float* __restrict__ out) {
    const int e   = blockIdx.z;
    const int cnt = g_cnt[e];
    const int m0  = blockIdx.y * 32;
    if (m0 >= cnt) return;
    const int n0  = blockIdx.x * 128;

    __shared__ __align__(16) float As[2][32 * AP];
    __shared__ __align__(16) float Bs[2][16 * BP2];
    __shared__ int   toks[32];
    __shared__ float wts[32];

    const int tid = threadIdx.x;
    if (tid < 32) {
        int r = m0 + tid;
        if (r < cnt) {
            toks[tid] = g_tok[e * NTOK + r];
            wts[tid]  = g_wt [e * NTOK + r];
        } else {
            toks[tid] = -1;
            wts[tid]  = 0.f;
        }
    }
    __syncthreads();

    const bool aload = (tid < 128);
    const int  am = tid >> 2;
    const int  ac = (tid & 3) * 4;
    const float* aptr = g_act;
    if (aload) {
        int pk = toks[am];
        aptr = g_act + (size_t)(pk >= 0 ? pk : 0) * IDIM + ac;
    }
    const int bk = tid >> 4;             // 0..15
    const int bn = (tid & 15) * 8;       // 0..120 (2x float4)
    const size_t bstep = (size_t)16 * HDIM;
    const float* bp = wd + (size_t)e * IDIM * HDIM + (size_t)bk * HDIM + n0 + bn;

    const int lane = tid & 31, wid = tid >> 5;
    const int mw = (wid & 1) * 16;
    const int nw = (wid >> 1) * 32;
    const int g  = lane >> 2, q = lane & 3;

    float acc[4][4] = {};

    float4 rA = make_float4(0, 0, 0, 0), rB0, rB1;

    if (aload) rA = *(const float4*)aptr;
    rB0 = *(const float4*)bp;
    rB1 = *(const float4*)(bp + 4);
    if (aload) *(float4*)&As[0][am * AP + ac] = tf4(rA);
    *(float4*)&Bs[0][bk * BP2 + bn]     = tf4(rB0);
    *(float4*)&Bs[0][bk * BP2 + bn + 4] = tf4(rB1);
    __syncthreads();

    int p = 0;
    for (int k0 = 0; k0 < IDIM; k0 += 16) {
        const bool more = (k0 + 16 < IDIM);
        if (more) {
            aptr += 16; bp += bstep;
            if (aload) rA = *(const float4*)aptr;
            rB0 = *(const float4*)bp;
            rB1 = *(const float4*)(bp + 4);
        }

        #pragma unroll
        for (int kk = 0; kk < 16; kk += 8) {
            uint32_t a[4];
            const float* ab = &As[p][(mw + g) * AP + kk + q];
            a[0] = __float_as_uint(ab[0]);
            a[1] = __float_as_uint(ab[8 * AP]);
            a[2] = __float_as_uint(ab[4]);
            a[3] = __float_as_uint(ab[8 * AP + 4]);
            #pragma unroll
            for (int ni = 0; ni < 4; ni++) {
                const float* bb = &Bs[p][(kk + q) * BP2 + nw + ni * 8 + g];
                uint32_t bf[2] = { __float_as_uint(bb[0]), __float_as_uint(bb[4 * BP2]) };
                mma8(acc[ni], a, bf);
            }
        }

        if (more) {
            if (aload) *(float4*)&As[p ^ 1][am * AP + ac] = tf4(rA);
            *(float4*)&Bs[p ^ 1][bk * BP2 + bn]     = tf4(rB0);
            *(float4*)&Bs[p ^ 1][bk * BP2 + bn + 4] = tf4(rB1);
        }
        __syncthreads();
        p ^= 1;
    }

    // ---- epilogue: weighted atomic scatter
    #pragma unroll
    for (int half = 0; half < 2; half++) {
        int row = mw + g + half * 8;
        int pk  = toks[row];
        if (pk < 0) continue;
        float w   = wts[row];
        int   tok = pk >> 1;
        float* dst = out + (size_t)tok * HDIM + n0 + nw + 2 * q;
        #pragma unroll
        for (int ni = 0; ni < 4; ni++) {
            atomicAdd(dst + ni * 8 + 0, w * acc[ni][half * 2 + 0]);
            atomicAdd(dst + ni * 8 + 1, w * acc[ni][half * 2 + 1]);
        }
    }
}

// ---------------- launch ----------------------------------------------------
extern "C" void kernel_launch(void* const* d_in, const int* in_sizes, int n_in,
                              void* d_out, int out_size) {
    const float* x   = (const float*)d_in[0];  // [1024, 2048]
    const float* gw  = (const float*)d_in[1];  // [E, H]
    const float* wg  = (const float*)d_in[2];  // [E, H, I]
    const float* wu  = (const float*)d_in[3];  // [E, H, I]
    const float* wd  = (const float*)d_in[4];  // [E, I, H]
    float* out = (float*)d_out;                // [1024, 2048] f32

    cudaMemsetAsync(out, 0, (size_t)NTOK * HDIM * sizeof(float), 0);
    zero_counts_kernel<<<1, 32>>>();
    router_kernel<<<NTOK, 256>>>(x, gw);

    dim3 g1(IDIM / 64, NTOK / 32, NEXP);    // (22, 32, 16); dead tiles exit fast
    gemm1_tc<<<g1, 256>>>(x, wg, wu);

    dim3 g2(HDIM / 128, NTOK / 32, NEXP);   // (16, 32, 16)
    gemm2_tc<<<g2, 256>>>(wd, out);
}